// round 16
// baseline (speedup 1.0000x reference)
#include <cuda_runtime.h>
#include <cuda_fp16.h>

#define NN   10000
#define EE   640000
#define KDIM 128
#define CAP  160

#define SCAT_BLOCKS 625             // 625*256*4 = 640000 edges
#define RB          313             // ceil(10000/32) row blocks of 32
#define G0_BLOCKS   (RB * 2)        // layer-0: 313 x 2 col-blocks of 64
#define WC1_BLOCKS  16              // W1: 128*128 f32 = 4096 float4
#define WC2_BLOCKS  8               // W2: 128*64  f32 = 2048 float4
#define FUSED_BLOCKS (SCAT_BLOCKS + G0_BLOCKS + WC1_BLOCKS + WC2_BLOCKS)
#define AGG_BLOCKS  1250            // 10000 warps

#define APAD 136                    // A-tile smem row stride (halves)
#define BPAD 72                     // B-tile smem row stride (64 + 8)

// ---------------- scratch (device globals, no allocation) ----------------
// g_cnt starts zero-initialized (CUDA static init) and is re-zeroed by agg64
// at the end of every launch, so each call sees zeroed counters.
__device__ int    g_cnt[NN];
__device__ int    g_eb[NN * CAP];
__device__ __half g_zh0[NN * KDIM];
__device__ __half g_zh1[NN * KDIM];
__device__ __half g_zh2[NN * 64];
__device__ __half g_h16[NN * KDIM];        // agg output (next GEMM A operand)
__device__ __half g_w1h[KDIM * KDIM];
__device__ __half g_w2h[KDIM * 64];

__device__ __forceinline__ __half2 u2h(unsigned u) { return *reinterpret_cast<__half2*>(&u); }

__device__ __forceinline__ uint2 f4_to_h4(float4 v) {
    __half2 h0 = __floats2half2_rn(v.x, v.y);
    __half2 h1 = __floats2half2_rn(v.z, v.w);
    uint2 r;
    r.x = *(unsigned*)&h0;
    r.y = *(unsigned*)&h1;
    return r;
}

__device__ __forceinline__ float4 h4_to_f4(uint2 r) {
    float2 f0 = __half22float2(u2h(r.x));
    float2 f1 = __half22float2(u2h(r.y));
    return make_float4(f0.x, f0.y, f1.x, f1.y);
}

// ---------------- mma helpers ----------------
__device__ __forceinline__ unsigned smem_u32(const void* p) {
    return (unsigned)__cvta_generic_to_shared(p);
}
__device__ __forceinline__ void ldsm_x4(unsigned& r0, unsigned& r1, unsigned& r2, unsigned& r3,
                                        unsigned addr) {
    asm volatile("ldmatrix.sync.aligned.m8n8.x4.shared.b16 {%0,%1,%2,%3}, [%4];"
                 : "=r"(r0), "=r"(r1), "=r"(r2), "=r"(r3) : "r"(addr));
}
__device__ __forceinline__ void ldsm_x4_t(unsigned& r0, unsigned& r1, unsigned& r2, unsigned& r3,
                                          unsigned addr) {
    asm volatile("ldmatrix.sync.aligned.m8n8.x4.trans.shared.b16 {%0,%1,%2,%3}, [%4];"
                 : "=r"(r0), "=r"(r1), "=r"(r2), "=r"(r3) : "r"(addr));
}
__device__ __forceinline__ void mma_16816(float* c, unsigned a0, unsigned a1, unsigned a2,
                                          unsigned a3, unsigned b0, unsigned b1) {
    asm volatile(
        "mma.sync.aligned.m16n8k16.row.col.f32.f16.f16.f32 "
        "{%0,%1,%2,%3}, {%4,%5,%6,%7}, {%8,%9}, {%0,%1,%2,%3};"
        : "+f"(c[0]), "+f"(c[1]), "+f"(c[2]), "+f"(c[3])
        : "r"(a0), "r"(a1), "r"(a2), "r"(a3), "r"(b0), "r"(b1));
}

// MMA mainloop + fp16 epilogue: 32x64 tile, 8 warps (16x16 warp tiles)
__device__ __forceinline__ void mma_tile_32x64(const __half* As, const __half* Bs,
                                               __half* __restrict__ zhout,
                                               int M, int Nc, int bm, int bn) {
    int tid = threadIdx.x;
    int wid = tid >> 5, lane = tid & 31;
    int wm = (wid & 1) * 16;
    int wn = (wid >> 1) * 16;
    float c[2][4] = {};
    int jhi = lane >> 3;
#pragma unroll
    for (int ks = 0; ks < 8; ks++) {
        unsigned a0, a1, a2, a3;
        ldsm_x4(a0, a1, a2, a3,
                smem_u32(As + (wm + (lane & 15)) * APAD + (lane >> 4) * 8 + ks * 16));
        int krow = ks * 16 + (jhi & 1) * 8 + (lane & 7);
        int ncol = wn + (jhi >> 1) * 8;
        unsigned b0, b1, b2, b3;
        ldsm_x4_t(b0, b1, b2, b3, smem_u32(Bs + krow * BPAD + ncol));
        mma_16816(c[0], a0, a1, a2, a3, b0, b1);
        mma_16816(c[1], a0, a1, a2, a3, b2, b3);
    }
    int r0 = bm + wm + (lane >> 2);
    int col0 = bn + wn + (lane & 3) * 2;
#pragma unroll
    for (int t = 0; t < 2; t++) {
        int col = col0 + t * 8;
        if (r0 < M)
            *(__half2*)(zhout + (size_t)r0 * Nc + col) = __floats2half2_rn(c[t][0], c[t][1]);
        int r1 = r0 + 8;
        if (r1 < M)
            *(__half2*)(zhout + (size_t)r1 * Nc + col) = __floats2half2_rn(c[t][2], c[t][3]);
    }
}

// ---------------- layer-0 GEMM body (fp32 inputs, inline cvt) ----------------
__device__ __forceinline__ void gemm0_body(const float* __restrict__ feat,
                                           const float* __restrict__ W0, int bm, int bn) {
    __shared__ __half As[32 * APAD];
    __shared__ __half Bs[128 * BPAD];
    int tid = threadIdx.x;
    // A: 32 rows x 128 f32 -> fp16 (1024 float4)
#pragma unroll
    for (int i = 0; i < 4; i++) {
        int idx = tid + i * 256;
        int row = idx >> 5, c4 = idx & 31;
        int grow = bm + row;
        float4 v = make_float4(0, 0, 0, 0);
        if (grow < NN) v = *(const float4*)(feat + (size_t)grow * KDIM + c4 * 4);
        *(uint2*)(As + row * APAD + c4 * 4) = f4_to_h4(v);
    }
    // B: 128 rows x 64-col slice f32 -> fp16 (2048 float4)
#pragma unroll
    for (int i = 0; i < 8; i++) {
        int idx = tid + i * 256;
        int row = idx >> 4, c4 = idx & 15;
        float4 v = *(const float4*)(W0 + (size_t)row * KDIM + bn + c4 * 4);
        *(uint2*)(Bs + row * BPAD + c4 * 4) = f4_to_h4(v);
    }
    __syncthreads();
    mma_tile_32x64(As, Bs, g_zh0, NN, 128, bm, bn);
}

// ---------------- fused: scatter || layer-0 GEMM || W1/W2 cvt ----------------
__global__ void fused_l0_kernel(const float* __restrict__ feat, const float* __restrict__ W0,
                                const float* __restrict__ W1, const float* __restrict__ W2,
                                const int* __restrict__ src, const int* __restrict__ dst) {
    int b = blockIdx.x;
    if (b < SCAT_BLOCKS) {
        int t = b * blockDim.x + threadIdx.x;   // one thread = 4 edges
        int4 dv = ((const int4*)dst)[t];
        int4 sv = ((const int4*)src)[t];
        int p0 = atomicAdd(&g_cnt[dv.x], 1);
        int p1 = atomicAdd(&g_cnt[dv.y], 1);
        int p2 = atomicAdd(&g_cnt[dv.z], 1);
        int p3 = atomicAdd(&g_cnt[dv.w], 1);
        g_eb[dv.x * CAP + p0] = sv.x;
        g_eb[dv.y * CAP + p1] = sv.y;
        g_eb[dv.z * CAP + p2] = sv.z;
        g_eb[dv.w * CAP + p3] = sv.w;
    } else if (b < SCAT_BLOCKS + G0_BLOCKS) {
        int gb = b - SCAT_BLOCKS;
        gemm0_body(feat, W0, (gb >> 1) * 32, (gb & 1) * 64);
    } else if (b < SCAT_BLOCKS + G0_BLOCKS + WC1_BLOCKS) {
        int i = (b - SCAT_BLOCKS - G0_BLOCKS) * 256 + threadIdx.x;
        ((uint2*)g_w1h)[i] = f4_to_h4(((const float4*)W1)[i]);
    } else {
        int i = (b - SCAT_BLOCKS - G0_BLOCKS - WC1_BLOCKS) * 256 + threadIdx.x;
        ((uint2*)g_w2h)[i] = f4_to_h4(((const float4*)W2)[i]);
    }
}

// ---------------- GEMM (fp16 A, fp16 B) -> fp16 out, 32x64 tiles ----------------
__global__ void gemm_mma_kernel(const __half* __restrict__ A16, const __half* __restrict__ B16,
                                __half* __restrict__ zhout, int M, int Nc) {
    __shared__ __half As[32 * APAD];
    __shared__ __half Bs[128 * BPAD];
    int tid = threadIdx.x;
    int bm = blockIdx.x * 32, bn = blockIdx.y * 64;
    // A: 32 rows x 128 halves = 512 uint4
#pragma unroll
    for (int i = 0; i < 2; i++) {
        int idx = tid + i * 256;
        int row = idx >> 4, c8 = idx & 15;
        int grow = bm + row;
        uint4 v = make_uint4(0, 0, 0, 0);
        if (grow < M) v = *(const uint4*)(A16 + (size_t)grow * KDIM + c8 * 8);
        *(uint4*)(As + row * APAD + c8 * 8) = v;
    }
    // B: 128 rows x 64 halves = 1024 uint4
#pragma unroll
    for (int i = 0; i < 4; i++) {
        int idx = tid + i * 256;
        int row = idx >> 3, c8 = idx & 7;
        uint4 v = *(const uint4*)(B16 + (size_t)row * Nc + bn + c8 * 8);
        *(uint4*)(Bs + row * BPAD + c8 * 8) = v;
    }
    __syncthreads();
    mma_tile_32x64(As, Bs, zhout, M, Nc, bm, bn);
}

// ---------------- aggregation (128 cols): h16[v] = zh[v] + sum zh[u] ----------------
__global__ void agg128_kernel(const __half* __restrict__ zh, __half* __restrict__ outh) {
    int gw = (blockIdx.x * blockDim.x + threadIdx.x) >> 5;
    if (gw >= NN) return;
    int lane = threadIdx.x & 31;
    const uint2* zh2 = (const uint2*)zh;

    float4 self = h4_to_f4(zh2[gw * 32 + lane]);
    float4 aA = make_float4(0, 0, 0, 0);
    float4 aB = make_float4(0, 0, 0, 0);

    int n = g_cnt[gw];
    int s = gw * CAP;
    int j = 0;
    for (; j + 8 <= n; j += 8) {
        int4 i0 = *(const int4*)&g_eb[s + j];
        int4 i1 = *(const int4*)&g_eb[s + j + 4];
        uint2 v0 = zh2[i0.x * 32 + lane];
        uint2 v1 = zh2[i0.y * 32 + lane];
        uint2 v2 = zh2[i0.z * 32 + lane];
        uint2 v3 = zh2[i0.w * 32 + lane];
        uint2 v4 = zh2[i1.x * 32 + lane];
        uint2 v5 = zh2[i1.y * 32 + lane];
        uint2 v6 = zh2[i1.z * 32 + lane];
        uint2 v7 = zh2[i1.w * 32 + lane];
        __half2 gAx = __hadd2(__hadd2(u2h(v0.x), u2h(v1.x)), __hadd2(u2h(v2.x), u2h(v3.x)));
        __half2 gAy = __hadd2(__hadd2(u2h(v0.y), u2h(v1.y)), __hadd2(u2h(v2.y), u2h(v3.y)));
        __half2 gBx = __hadd2(__hadd2(u2h(v4.x), u2h(v5.x)), __hadd2(u2h(v6.x), u2h(v7.x)));
        __half2 gBy = __hadd2(__hadd2(u2h(v4.y), u2h(v5.y)), __hadd2(u2h(v6.y), u2h(v7.y)));
        float2 fa0 = __half22float2(gAx);
        float2 fa1 = __half22float2(gAy);
        float2 fb0 = __half22float2(gBx);
        float2 fb1 = __half22float2(gBy);
        aA.x += fa0.x; aA.y += fa0.y; aA.z += fa1.x; aA.w += fa1.y;
        aB.x += fb0.x; aB.y += fb0.y; aB.z += fb1.x; aB.w += fb1.y;
    }
    for (; j < n; j++) {
        uint2 v = zh2[g_eb[s + j] * 32 + lane];
        float2 f0 = __half22float2(u2h(v.x));
        float2 f1 = __half22float2(u2h(v.y));
        aA.x += f0.x; aA.y += f0.y; aA.z += f1.x; aA.w += f1.y;
    }
    __half2 h0 = __floats2half2_rn(self.x + aA.x + aB.x, self.y + aA.y + aB.y);
    __half2 h1 = __floats2half2_rn(self.z + aA.z + aB.z, self.w + aA.w + aB.w);
    uint2 hp;
    hp.x = *(unsigned*)&h0;
    hp.y = *(unsigned*)&h1;
    ((uint2*)outh)[gw * 32 + lane] = hp;
}

// ---------------- final aggregation (64 cols) -> fp32 out, resets counters ----------------
__global__ void agg64_kernel(const __half* __restrict__ zh, float* __restrict__ out) {
    int gw = (blockIdx.x * blockDim.x + threadIdx.x) >> 5;
    if (gw >= NN) return;
    int lane = threadIdx.x & 31;
    const unsigned* zhu = (const unsigned*)zh;

    float2 self = __half22float2(u2h(zhu[gw * 32 + lane]));
    float2 aA = make_float2(0, 0);
    float2 aB = make_float2(0, 0);

    int n = g_cnt[gw];
    // reset counter for the next launch (replay) -- lane 0 only
    if (lane == 0) g_cnt[gw] = 0;

    int s = gw * CAP;
    int j = 0;
    for (; j + 8 <= n; j += 8) {
        int4 i0 = *(const int4*)&g_eb[s + j];
        int4 i1 = *(const int4*)&g_eb[s + j + 4];
        unsigned v0 = zhu[i0.x * 32 + lane];
        unsigned v1 = zhu[i0.y * 32 + lane];
        unsigned v2 = zhu[i0.z * 32 + lane];
        unsigned v3 = zhu[i0.w * 32 + lane];
        unsigned v4 = zhu[i1.x * 32 + lane];
        unsigned v5 = zhu[i1.y * 32 + lane];
        unsigned v6 = zhu[i1.z * 32 + lane];
        unsigned v7 = zhu[i1.w * 32 + lane];
        __half2 gA = __hadd2(__hadd2(u2h(v0), u2h(v1)), __hadd2(u2h(v2), u2h(v3)));
        __half2 gB = __hadd2(__hadd2(u2h(v4), u2h(v5)), __hadd2(u2h(v6), u2h(v7)));
        float2 fa = __half22float2(gA);
        float2 fb = __half22float2(gB);
        aA.x += fa.x; aA.y += fa.y;
        aB.x += fb.x; aB.y += fb.y;
    }
    for (; j < n; j++) {
        float2 f = __half22float2(u2h(zhu[g_eb[s + j] * 32 + lane]));
        aA.x += f.x; aA.y += f.y;
    }
    float2 r;
    r.x = self.x + aA.x + aB.x;
    r.y = self.y + aA.y + aB.y;
    ((float2*)out)[gw * 32 + lane] = r;
}

// ---------------- launch ----------------
extern "C" void kernel_launch(void* const* d_in, const int* in_sizes, int n_in,
                              void* d_out, int out_size) {
    const float* feat = (const float*)d_in[0];
    const float* W0   = (const float*)d_in[1];
    const float* W1   = (const float*)d_in[2];
    const float* W2   = (const float*)d_in[3];
    const int*   src  = (const int*)d_in[4];
    const int*   dst  = (const int*)d_in[5];
    float*       out  = (float*)d_out;

    void *pzh0, *pzh1, *pzh2, *ph16, *pw1, *pw2;
    cudaGetSymbolAddress(&pzh0, g_zh0);
    cudaGetSymbolAddress(&pzh1, g_zh1);
    cudaGetSymbolAddress(&pzh2, g_zh2);
    cudaGetSymbolAddress(&ph16, g_h16);
    cudaGetSymbolAddress(&pw1, g_w1h);
    cudaGetSymbolAddress(&pw2, g_w2h);
    __half* h16 = (__half*)ph16;

    // scatter || layer-0 GEMM (inline fp16 cvt) || W1/W2 cvt
    // (g_cnt is zero on entry: static init on first call, agg64 resets it after)
    fused_l0_kernel<<<FUSED_BLOCKS, 256>>>(feat, W0, W1, W2, src, dst);
    // layer 1: agg(zh0) -> h16 ; h16 @ W1 -> zh1
    agg128_kernel<<<AGG_BLOCKS, 256>>>((const __half*)pzh0, h16);
    gemm_mma_kernel<<<dim3(RB, 2), 256>>>(h16, (const __half*)pw1, (__half*)pzh1, NN, 128);
    // layer 2: agg(zh1) -> h16 ; h16 @ W2 -> zh2 (64 cols)
    agg128_kernel<<<AGG_BLOCKS, 256>>>((const __half*)pzh1, h16);
    gemm_mma_kernel<<<dim3(RB, 1), 256>>>(h16, (const __half*)pw2, (__half*)pzh2, NN, 64);
    // final aggregation -> fp32 out (also resets g_cnt for next call)
    agg64_kernel<<<AGG_BLOCKS, 256>>>((const __half*)pzh2, out);
}

// round 17
// speedup vs baseline: 1.0726x; 1.0726x over previous
#include <cuda_runtime.h>
#include <cuda_fp16.h>

#define NN   10000
#define EE   640000
#define KDIM 128
#define CAP  160

#define SCAT_BLOCKS 625             // 625*256*4 = 640000 edges
#define RB          313             // ceil(10000/32) row blocks of 32
#define G0_BLOCKS   (RB * 2)        // layer-0: 313 x 2 col-blocks of 64
#define WC1_BLOCKS  16              // W1: 128*128 f32 = 4096 float4
#define WC2_BLOCKS  8               // W2: 128*64  f32 = 2048 float4
#define FUSED_BLOCKS (SCAT_BLOCKS + G0_BLOCKS + WC1_BLOCKS + WC2_BLOCKS)
#define AGG_BLOCKS  1250            // 10000 warps

#define APAD 136                    // A-tile smem row stride (halves)
#define BPAD 72                     // B-tile smem row stride (64 + 8)

// ---------------- scratch (device globals, no allocation) ----------------
__device__ int    g_cnt[NN];
__device__ int    g_eb[NN * CAP];
__device__ __half g_zh0[NN * KDIM];
__device__ __half g_zh1[NN * KDIM];
__device__ __half g_zh2[NN * 64];
__device__ __half g_h16[NN * KDIM];        // agg output (next GEMM A operand)
__device__ __half g_w1h[KDIM * KDIM];
__device__ __half g_w2h[KDIM * 64];

__device__ __forceinline__ __half2 u2h(unsigned u) { return *reinterpret_cast<__half2*>(&u); }

__device__ __forceinline__ uint2 f4_to_h4(float4 v) {
    __half2 h0 = __floats2half2_rn(v.x, v.y);
    __half2 h1 = __floats2half2_rn(v.z, v.w);
    uint2 r;
    r.x = *(unsigned*)&h0;
    r.y = *(unsigned*)&h1;
    return r;
}

__device__ __forceinline__ float4 h4_to_f4(uint2 r) {
    float2 f0 = __half22float2(u2h(r.x));
    float2 f1 = __half22float2(u2h(r.y));
    return make_float4(f0.x, f0.y, f1.x, f1.y);
}

// ---------------- zero counters ----------------
__global__ void zero_cnt_kernel() {
    int i = blockIdx.x * blockDim.x + threadIdx.x;
    if (i < NN / 4) ((int4*)g_cnt)[i] = make_int4(0, 0, 0, 0);
}

// ---------------- mma helpers ----------------
__device__ __forceinline__ unsigned smem_u32(const void* p) {
    return (unsigned)__cvta_generic_to_shared(p);
}
__device__ __forceinline__ void ldsm_x4(unsigned& r0, unsigned& r1, unsigned& r2, unsigned& r3,
                                        unsigned addr) {
    asm volatile("ldmatrix.sync.aligned.m8n8.x4.shared.b16 {%0,%1,%2,%3}, [%4];"
                 : "=r"(r0), "=r"(r1), "=r"(r2), "=r"(r3) : "r"(addr));
}
__device__ __forceinline__ void ldsm_x4_t(unsigned& r0, unsigned& r1, unsigned& r2, unsigned& r3,
                                          unsigned addr) {
    asm volatile("ldmatrix.sync.aligned.m8n8.x4.trans.shared.b16 {%0,%1,%2,%3}, [%4];"
                 : "=r"(r0), "=r"(r1), "=r"(r2), "=r"(r3) : "r"(addr));
}
__device__ __forceinline__ void mma_16816(float* c, unsigned a0, unsigned a1, unsigned a2,
                                          unsigned a3, unsigned b0, unsigned b1) {
    asm volatile(
        "mma.sync.aligned.m16n8k16.row.col.f32.f16.f16.f32 "
        "{%0,%1,%2,%3}, {%4,%5,%6,%7}, {%8,%9}, {%0,%1,%2,%3};"
        : "+f"(c[0]), "+f"(c[1]), "+f"(c[2]), "+f"(c[3])
        : "r"(a0), "r"(a1), "r"(a2), "r"(a3), "r"(b0), "r"(b1));
}

// MMA mainloop + fp16 epilogue: 32x64 tile, 8 warps (16x16 warp tiles)
__device__ __forceinline__ void mma_tile_32x64(const __half* As, const __half* Bs,
                                               __half* __restrict__ zhout,
                                               int M, int Nc, int bm, int bn) {
    int tid = threadIdx.x;
    int wid = tid >> 5, lane = tid & 31;
    int wm = (wid & 1) * 16;
    int wn = (wid >> 1) * 16;
    float c[2][4] = {};
    int jhi = lane >> 3;
#pragma unroll
    for (int ks = 0; ks < 8; ks++) {
        unsigned a0, a1, a2, a3;
        ldsm_x4(a0, a1, a2, a3,
                smem_u32(As + (wm + (lane & 15)) * APAD + (lane >> 4) * 8 + ks * 16));
        int krow = ks * 16 + (jhi & 1) * 8 + (lane & 7);
        int ncol = wn + (jhi >> 1) * 8;
        unsigned b0, b1, b2, b3;
        ldsm_x4_t(b0, b1, b2, b3, smem_u32(Bs + krow * BPAD + ncol));
        mma_16816(c[0], a0, a1, a2, a3, b0, b1);
        mma_16816(c[1], a0, a1, a2, a3, b2, b3);
    }
    int r0 = bm + wm + (lane >> 2);
    int col0 = bn + wn + (lane & 3) * 2;
#pragma unroll
    for (int t = 0; t < 2; t++) {
        int col = col0 + t * 8;
        if (r0 < M)
            *(__half2*)(zhout + (size_t)r0 * Nc + col) = __floats2half2_rn(c[t][0], c[t][1]);
        int r1 = r0 + 8;
        if (r1 < M)
            *(__half2*)(zhout + (size_t)r1 * Nc + col) = __floats2half2_rn(c[t][2], c[t][3]);
    }
}

// ---------------- layer-0 GEMM body (fp32 inputs, inline cvt) ----------------
__device__ __forceinline__ void gemm0_body(const float* __restrict__ feat,
                                           const float* __restrict__ W0, int bm, int bn) {
    __shared__ __half As[32 * APAD];
    __shared__ __half Bs[128 * BPAD];
    int tid = threadIdx.x;
    // A: 32 rows x 128 f32 -> fp16 (1024 float4)
#pragma unroll
    for (int i = 0; i < 4; i++) {
        int idx = tid + i * 256;
        int row = idx >> 5, c4 = idx & 31;
        int grow = bm + row;
        float4 v = make_float4(0, 0, 0, 0);
        if (grow < NN) v = *(const float4*)(feat + (size_t)grow * KDIM + c4 * 4);
        *(uint2*)(As + row * APAD + c4 * 4) = f4_to_h4(v);
    }
    // B: 128 rows x 64-col slice f32 -> fp16 (2048 float4)
#pragma unroll
    for (int i = 0; i < 8; i++) {
        int idx = tid + i * 256;
        int row = idx >> 4, c4 = idx & 15;
        float4 v = *(const float4*)(W0 + (size_t)row * KDIM + bn + c4 * 4);
        *(uint2*)(Bs + row * BPAD + c4 * 4) = f4_to_h4(v);
    }
    __syncthreads();
    mma_tile_32x64(As, Bs, g_zh0, NN, 128, bm, bn);
}

// ---------------- fused: scatter || layer-0 GEMM || W1/W2 cvt ----------------
__global__ void fused_l0_kernel(const float* __restrict__ feat, const float* __restrict__ W0,
                                const float* __restrict__ W1, const float* __restrict__ W2,
                                const int* __restrict__ src, const int* __restrict__ dst) {
    int b = blockIdx.x;
    if (b < SCAT_BLOCKS) {
        int t = b * blockDim.x + threadIdx.x;   // one thread = 4 edges
        int4 dv = ((const int4*)dst)[t];
        int4 sv = ((const int4*)src)[t];
        int p0 = atomicAdd(&g_cnt[dv.x], 1);
        int p1 = atomicAdd(&g_cnt[dv.y], 1);
        int p2 = atomicAdd(&g_cnt[dv.z], 1);
        int p3 = atomicAdd(&g_cnt[dv.w], 1);
        g_eb[dv.x * CAP + p0] = sv.x;
        g_eb[dv.y * CAP + p1] = sv.y;
        g_eb[dv.z * CAP + p2] = sv.z;
        g_eb[dv.w * CAP + p3] = sv.w;
    } else if (b < SCAT_BLOCKS + G0_BLOCKS) {
        int gb = b - SCAT_BLOCKS;
        gemm0_body(feat, W0, (gb >> 1) * 32, (gb & 1) * 64);
    } else if (b < SCAT_BLOCKS + G0_BLOCKS + WC1_BLOCKS) {
        int i = (b - SCAT_BLOCKS - G0_BLOCKS) * 256 + threadIdx.x;
        ((uint2*)g_w1h)[i] = f4_to_h4(((const float4*)W1)[i]);
    } else {
        int i = (b - SCAT_BLOCKS - G0_BLOCKS - WC1_BLOCKS) * 256 + threadIdx.x;
        ((uint2*)g_w2h)[i] = f4_to_h4(((const float4*)W2)[i]);
    }
}

// ---------------- GEMM (fp16 A, fp16 B) -> fp16 out, 32x64 tiles ----------------
__global__ void gemm_mma_kernel(const __half* __restrict__ A16, const __half* __restrict__ B16,
                                __half* __restrict__ zhout, int M, int Nc) {
    __shared__ __half As[32 * APAD];
    __shared__ __half Bs[128 * BPAD];
    int tid = threadIdx.x;
    int bm = blockIdx.x * 32, bn = blockIdx.y * 64;
    // A: 32 rows x 128 halves = 512 uint4
#pragma unroll
    for (int i = 0; i < 2; i++) {
        int idx = tid + i * 256;
        int row = idx >> 4, c8 = idx & 15;
        int grow = bm + row;
        uint4 v = make_uint4(0, 0, 0, 0);
        if (grow < M) v = *(const uint4*)(A16 + (size_t)grow * KDIM + c8 * 8);
        *(uint4*)(As + row * APAD + c8 * 8) = v;
    }
    // B: 128 rows x 64 halves = 1024 uint4
#pragma unroll
    for (int i = 0; i < 4; i++) {
        int idx = tid + i * 256;
        int row = idx >> 3, c8 = idx & 7;
        uint4 v = *(const uint4*)(B16 + (size_t)row * Nc + bn + c8 * 8);
        *(uint4*)(Bs + row * BPAD + c8 * 8) = v;
    }
    __syncthreads();
    mma_tile_32x64(As, Bs, zhout, M, Nc, bm, bn);
}

// ---------------- aggregation (128 cols): h16[v] = zh[v] + sum zh[u] ----------------
__global__ void __launch_bounds__(256, 6)
agg128_kernel(const __half* __restrict__ zh, __half* __restrict__ outh) {
    int gw = (blockIdx.x * blockDim.x + threadIdx.x) >> 5;
    if (gw >= NN) return;
    int lane = threadIdx.x & 31;
    const uint2* zh2 = (const uint2*)zh;

    float4 self = h4_to_f4(zh2[gw * 32 + lane]);
    float4 aA = make_float4(0, 0, 0, 0);
    float4 aB = make_float4(0, 0, 0, 0);

    int n = g_cnt[gw];
    int s = gw * CAP;
    int j = 0;
    for (; j + 8 <= n; j += 8) {
        int4 i0 = *(const int4*)&g_eb[s + j];
        int4 i1 = *(const int4*)&g_eb[s + j + 4];
        uint2 v0 = zh2[i0.x * 32 + lane];
        uint2 v1 = zh2[i0.y * 32 + lane];
        uint2 v2 = zh2[i0.z * 32 + lane];
        uint2 v3 = zh2[i0.w * 32 + lane];
        uint2 v4 = zh2[i1.x * 32 + lane];
        uint2 v5 = zh2[i1.y * 32 + lane];
        uint2 v6 = zh2[i1.z * 32 + lane];
        uint2 v7 = zh2[i1.w * 32 + lane];
        __half2 gAx = __hadd2(__hadd2(u2h(v0.x), u2h(v1.x)), __hadd2(u2h(v2.x), u2h(v3.x)));
        __half2 gAy = __hadd2(__hadd2(u2h(v0.y), u2h(v1.y)), __hadd2(u2h(v2.y), u2h(v3.y)));
        __half2 gBx = __hadd2(__hadd2(u2h(v4.x), u2h(v5.x)), __hadd2(u2h(v6.x), u2h(v7.x)));
        __half2 gBy = __hadd2(__hadd2(u2h(v4.y), u2h(v5.y)), __hadd2(u2h(v6.y), u2h(v7.y)));
        float2 fa0 = __half22float2(gAx);
        float2 fa1 = __half22float2(gAy);
        float2 fb0 = __half22float2(gBx);
        float2 fb1 = __half22float2(gBy);
        aA.x += fa0.x; aA.y += fa0.y; aA.z += fa1.x; aA.w += fa1.y;
        aB.x += fb0.x; aB.y += fb0.y; aB.z += fb1.x; aB.w += fb1.y;
    }
    for (; j < n; j++) {
        uint2 v = zh2[g_eb[s + j] * 32 + lane];
        float2 f0 = __half22float2(u2h(v.x));
        float2 f1 = __half22float2(u2h(v.y));
        aA.x += f0.x; aA.y += f0.y; aA.z += f1.x; aA.w += f1.y;
    }
    __half2 h0 = __floats2half2_rn(self.x + aA.x + aB.x, self.y + aA.y + aB.y);
    __half2 h1 = __floats2half2_rn(self.z + aA.z + aB.z, self.w + aA.w + aB.w);
    uint2 hp;
    hp.x = *(unsigned*)&h0;
    hp.y = *(unsigned*)&h1;
    ((uint2*)outh)[gw * 32 + lane] = hp;
}

// ---------------- final aggregation (64 cols) -> fp32 out ----------------
__global__ void __launch_bounds__(256, 6)
agg64_kernel(const __half* __restrict__ zh, float* __restrict__ out) {
    int gw = (blockIdx.x * blockDim.x + threadIdx.x) >> 5;
    if (gw >= NN) return;
    int lane = threadIdx.x & 31;
    const unsigned* zhu = (const unsigned*)zh;

    float2 self = __half22float2(u2h(zhu[gw * 32 + lane]));
    float2 aA = make_float2(0, 0);
    float2 aB = make_float2(0, 0);

    int n = g_cnt[gw];
    int s = gw * CAP;
    int j = 0;
    for (; j + 8 <= n; j += 8) {
        int4 i0 = *(const int4*)&g_eb[s + j];
        int4 i1 = *(const int4*)&g_eb[s + j + 4];
        unsigned v0 = zhu[i0.x * 32 + lane];
        unsigned v1 = zhu[i0.y * 32 + lane];
        unsigned v2 = zhu[i0.z * 32 + lane];
        unsigned v3 = zhu[i0.w * 32 + lane];
        unsigned v4 = zhu[i1.x * 32 + lane];
        unsigned v5 = zhu[i1.y * 32 + lane];
        unsigned v6 = zhu[i1.z * 32 + lane];
        unsigned v7 = zhu[i1.w * 32 + lane];
        __half2 gA = __hadd2(__hadd2(u2h(v0), u2h(v1)), __hadd2(u2h(v2), u2h(v3)));
        __half2 gB = __hadd2(__hadd2(u2h(v4), u2h(v5)), __hadd2(u2h(v6), u2h(v7)));
        float2 fa = __half22float2(gA);
        float2 fb = __half22float2(gB);
        aA.x += fa.x; aA.y += fa.y;
        aB.x += fb.x; aB.y += fb.y;
    }
    for (; j < n; j++) {
        float2 f = __half22float2(u2h(zhu[g_eb[s + j] * 32 + lane]));
        aA.x += f.x; aA.y += f.y;
    }
    float2 r;
    r.x = self.x + aA.x + aB.x;
    r.y = self.y + aA.y + aB.y;
    ((float2*)out)[gw * 32 + lane] = r;
}

// ---------------- launch ----------------
extern "C" void kernel_launch(void* const* d_in, const int* in_sizes, int n_in,
                              void* d_out, int out_size) {
    const float* feat = (const float*)d_in[0];
    const float* W0   = (const float*)d_in[1];
    const float* W1   = (const float*)d_in[2];
    const float* W2   = (const float*)d_in[3];
    const int*   src  = (const int*)d_in[4];
    const int*   dst  = (const int*)d_in[5];
    float*       out  = (float*)d_out;

    void *pzh0, *pzh1, *pzh2, *ph16, *pw1, *pw2;
    cudaGetSymbolAddress(&pzh0, g_zh0);
    cudaGetSymbolAddress(&pzh1, g_zh1);
    cudaGetSymbolAddress(&pzh2, g_zh2);
    cudaGetSymbolAddress(&ph16, g_h16);
    cudaGetSymbolAddress(&pw1, g_w1h);
    cudaGetSymbolAddress(&pw2, g_w2h);
    __half* h16 = (__half*)ph16;

    // zero counters (also pre-warms g_cnt lines into L2 before the scatter)
    zero_cnt_kernel<<<10, 256>>>();
    // scatter || layer-0 GEMM (inline fp16 cvt) || W1/W2 cvt
    fused_l0_kernel<<<FUSED_BLOCKS, 256>>>(feat, W0, W1, W2, src, dst);
    // layer 1: agg(zh0) -> h16 ; h16 @ W1 -> zh1
    agg128_kernel<<<AGG_BLOCKS, 256>>>((const __half*)pzh0, h16);
    gemm_mma_kernel<<<dim3(RB, 2), 256>>>(h16, (const __half*)pw1, (__half*)pzh1, NN, 128);
    // layer 2: agg(zh1) -> h16 ; h16 @ W2 -> zh2 (64 cols)
    agg128_kernel<<<AGG_BLOCKS, 256>>>((const __half*)pzh1, h16);
    gemm_mma_kernel<<<dim3(RB, 1), 256>>>(h16, (const __half*)pw2, (__half*)pzh2, NN, 64);
    // final aggregation -> fp32 out
    agg64_kernel<<<AGG_BLOCKS, 256>>>((const __half*)pzh2, out);
}